// round 3
// baseline (speedup 1.0000x reference)
#include <cuda_runtime.h>

// SGD_Hankel TT-chain: N=65536, L=128, D=4, R=8, O=2.  S=2 samples/thread.
// R3: latency-hiding round — cp.async double-buffered x chunks (no refill
// bursts, no syncwarp), unroll-3 step loop for cross-step core-LDS prefetch,
// exact-N (no guards).

#define DV 4
#define RV 8
#define LV 128
#define NSTEP 126
#define HALF  63

typedef unsigned long long u64;

__device__ __forceinline__ u64 fpack(float a, float b) {
    u64 r; asm("mov.b64 %0, {%1,%2};" : "=l"(r) : "f"(a), "f"(b)); return r;
}
__device__ __forceinline__ u64 fdup(float a) {
    u64 r; asm("mov.b64 %0, {%1,%1};" : "=l"(r) : "f"(a)); return r;
}
__device__ __forceinline__ void funpack(u64 v, float& a, float& b) {
    asm("mov.b64 {%0,%1}, %2;" : "=f"(a), "=f"(b) : "l"(v));
}
__device__ __forceinline__ u64 f2mul(u64 a, u64 b) {
    u64 d; asm("mul.rn.f32x2 %0, %1, %2;" : "=l"(d) : "l"(a), "l"(b)); return d;
}
__device__ __forceinline__ u64 f2fma(u64 a, u64 b, u64 c) {
    u64 d; asm("fma.rn.f32x2 %0, %1, %2, %3;" : "=l"(d) : "l"(a), "l"(b), "l"(c)); return d;
}

__device__ __forceinline__ void cpa16(unsigned dst, const void* src) {
    asm volatile("cp.async.cg.shared.global [%0], [%1], 16;" :: "r"(dst), "l"(src) : "memory");
}
__device__ __forceinline__ void cpa_commit() {
    asm volatile("cp.async.commit_group;" ::: "memory");
}
template<int N>
__device__ __forceinline__ void cpa_wait() {
    asm volatile("cp.async.wait_group %0;" :: "n"(N) : "memory");
}

// smem: phased cores [63][3][8][8] + xbuf 4 warps * (2 bufs * 4 steps * 64 rows * 16B) + first/last
#define SCORE_FLOATS (HALF * 3 * RV * RV)      // 12096
#define XBUF_FLOATS  (4 * 2048)                // 8192  (8KB per warp)
#define SFL_OFF      (SCORE_FLOATS + XBUF_FLOATS)
#define SMEM_FLOATS  (SFL_OFF + 96)
#define SMEM_BYTES   (SMEM_FLOATS * 4)         // 81536

// Issue one 4-step x chunk for this warp: 8 cp.async.cg 16B per thread.
// Layout: buf(c&1) -> [s4 0..3][row 0..63] float4  (rows 0..31 = samples A,
// 32..63 = samples B). Conflict-free without swizzle (consecutive 16B rows).
__device__ __forceinline__ void issue_chunk(const float* __restrict__ x,
                                            unsigned xw_b, int base_w, int lane, int c)
{
    const unsigned dbase = xw_b + (unsigned)((c & 1) * 4096);
    #pragma unroll
    for (int it = 0; it < 8; ++it) {
        const int s4   = it >> 1;
        const int bsel = it & 1;
        const int n    = base_w + lane + bsel * 128;
        const float* src = x + (size_t)n * (LV * DV) + (c * 4 + s4) * 4;
        const unsigned dst = dbase + (unsigned)((s4 * 64 + bsel * 32 + lane) * 16);
        cpa16(dst, src);
    }
    cpa_commit();
}

extern "C" __global__ void __launch_bounds__(128, 2)
tt_chain_kernel(const float* __restrict__ x,
                const float* __restrict__ core_first,
                const float* __restrict__ cores_mid,
                const float* __restrict__ core_last,
                float* __restrict__ out,
                int n_total)
{
    extern __shared__ float sm[];
    float* score  = sm;                    // [63][3][8][8]
    float* sfirst = sm + SFL_OFF;          // 32 floats [j][k]
    float* slast  = sfirst + 32;           // 64 floats [k][j][l]

    const int tid  = threadIdx.x;
    const int lane = tid & 31;
    const int w    = tid >> 5;
    float* xw = sm + SCORE_FLOATS + w * 2048;
    unsigned xw_b;
    { unsigned long long g = __cvta_generic_to_shared(xw); xw_b = (unsigned)g; }

    const int base_w = blockIdx.x * 256 + w * 32;
    const int n0 = base_w + lane;
    const int n1 = n0 + 128;

    // Kick off first two x chunks immediately (overlap with core staging).
    issue_chunk(x, xw_b, base_w, lane, 0);
    issue_chunk(x, xw_b, base_w, lane, 1);

    if (tid < 32)       sfirst[tid] = core_first[tid];
    else if (tid < 96)  slast[tid - 32] = core_last[tid - 32];

    u64 mpA[4], mpB[4];

    #pragma unroll 1
    for (int phase = 0; phase < 2; ++phase) {
        __syncthreads();    // prior-phase consumers done before core overwrite
        // stage cores for this phase: [s][k][j][l] -> [s][j][k][l], j<3
        for (int u = tid; u < HALF * 48; u += 128) {
            int st = u / 48;
            int rr = u - st * 48;
            int j = rr >> 4, k = (rr >> 1) & 7, h = rr & 1;
            float4 v = *(const float4*)(cores_mid
                        + (((size_t)(phase * HALF + st) * RV + k) * DV + j) * RV + h * 4);
            *(float4*)(score + ((st * 3 + j) * RV + k) * RV + h * 4) = v;
        }
        __syncthreads();

        if (phase == 0) {
            cpa_wait<1>();          // chunk 0 resident (chunk 1 may be in flight)
            float4 xa = *(const float4*)(xw + 0 * 256 + lane * 4);
            float4 xb = *(const float4*)(xw + 0 * 256 + 128 + lane * 4);
            float mA[8], mB[8];
            #pragma unroll
            for (int k = 0; k < 8; ++k) {
                mA[k] = sfirst[k] * xa.x + sfirst[8 + k] * xa.y
                      + sfirst[16 + k] * xa.z + sfirst[24 + k] * xa.w;
                mB[k] = sfirst[k] * xb.x + sfirst[8 + k] * xb.y
                      + sfirst[16 + k] * xb.z + sfirst[24 + k] * xb.w;
            }
            #pragma unroll
            for (int p = 0; p < 4; ++p) {
                mpA[p] = fpack(mA[2 * p], mA[2 * p + 1]);
                mpB[p] = fpack(mB[2 * p], mB[2 * p + 1]);
            }
        }

        const float* cp = score;
        #pragma unroll 3
        for (int sc = 0; sc < HALF; ++sc) {
            const int l = phase * HALF + sc + 1;       // x index consumed this step
            if ((l & 3) == 0) {
                // entering chunk c: buffer (c-1)&1 is free -> prefetch c+1 into it
                const int c = l >> 2;
                if (c < 31) {
                    issue_chunk(x, xw_b, base_w, lane, c + 1);
                    cpa_wait<1>();      // chunk c resident, c+1 in flight
                } else {
                    cpa_wait<0>();      // last chunk: drain
                }
            }
            const float* xc = xw + ((l >> 2) & 1) * 1024 + (l & 3) * 256;
            float4 xa = *(const float4*)(xc + lane * 4);
            float4 xb = *(const float4*)(xc + 128 + lane * 4);

            // duplicate merged scalars into packed lanes
            u64 mdA[8], mdB[8];
            #pragma unroll
            for (int p = 0; p < 4; ++p) {
                float a0, a1, b0, b1;
                funpack(mpA[p], a0, a1);
                funpack(mpB[p], b0, b1);
                mdA[2 * p] = fdup(a0); mdA[2 * p + 1] = fdup(a1);
                mdB[2 * p] = fdup(b0); mdB[2 * p + 1] = fdup(b1);
            }

            u64 Ya[3][4], Yb[3][4];
            #pragma unroll
            for (int j = 0; j < 3; ++j) {
                const float* cj = cp + j * 64;
                #pragma unroll
                for (int k = 0; k < 8; ++k) {
                    ulonglong2 cA = *(const ulonglong2*)(cj + k * 8);
                    ulonglong2 cB = *(const ulonglong2*)(cj + k * 8 + 4);
                    if (k == 0) {
                        Ya[j][0] = f2mul(mdA[0], cA.x); Ya[j][1] = f2mul(mdA[0], cA.y);
                        Ya[j][2] = f2mul(mdA[0], cB.x); Ya[j][3] = f2mul(mdA[0], cB.y);
                        Yb[j][0] = f2mul(mdB[0], cA.x); Yb[j][1] = f2mul(mdB[0], cA.y);
                        Yb[j][2] = f2mul(mdB[0], cB.x); Yb[j][3] = f2mul(mdB[0], cB.y);
                    } else {
                        Ya[j][0] = f2fma(mdA[k], cA.x, Ya[j][0]);
                        Ya[j][1] = f2fma(mdA[k], cA.y, Ya[j][1]);
                        Ya[j][2] = f2fma(mdA[k], cB.x, Ya[j][2]);
                        Ya[j][3] = f2fma(mdA[k], cB.y, Ya[j][3]);
                        Yb[j][0] = f2fma(mdB[k], cA.x, Yb[j][0]);
                        Yb[j][1] = f2fma(mdB[k], cA.y, Yb[j][1]);
                        Yb[j][2] = f2fma(mdB[k], cB.x, Yb[j][2]);
                        Yb[j][3] = f2fma(mdB[k], cB.y, Yb[j][3]);
                    }
                }
            }

            // identity slice: j=3 term is x3 * merged (exact)
            const u64 a0 = fdup(xa.x), a1 = fdup(xa.y), a2 = fdup(xa.z), a3 = fdup(xa.w);
            const u64 b0 = fdup(xb.x), b1 = fdup(xb.y), b2 = fdup(xb.z), b3 = fdup(xb.w);
            #pragma unroll
            for (int p = 0; p < 4; ++p) {
                mpA[p] = f2fma(a3, mpA[p],
                         f2fma(a2, Ya[2][p],
                         f2fma(a1, Ya[1][p],
                         f2mul(a0, Ya[0][p]))));
                mpB[p] = f2fma(b3, mpB[p],
                         f2fma(b2, Yb[2][p],
                         f2fma(b1, Yb[1][p],
                         f2mul(b0, Yb[0][p]))));
            }
            cp += 3 * 64;
        }
    }

    // ---- final contraction with core_last: out[l] = sum_j x_j (sum_k m_k C[k][j][l]) ----
    {
        const float* xc = xw + ((127 >> 2) & 1) * 1024 + (127 & 3) * 256;
        float4 xa = *(const float4*)(xc + lane * 4);
        float4 xb = *(const float4*)(xc + 128 + lane * 4);

        u64 mdA[8], mdB[8];
        #pragma unroll
        for (int p = 0; p < 4; ++p) {
            float a0, a1, b0, b1;
            funpack(mpA[p], a0, a1);
            funpack(mpB[p], b0, b1);
            mdA[2 * p] = fdup(a0); mdA[2 * p + 1] = fdup(a1);
            mdB[2 * p] = fdup(b0); mdB[2 * p + 1] = fdup(b1);
        }
        u64 YlA[4], YlB[4];
        #pragma unroll
        for (int j = 0; j < 4; ++j) {
            u64 accA = f2mul(mdA[0], *(const u64*)(slast + j * 2));
            u64 accB = f2mul(mdB[0], *(const u64*)(slast + j * 2));
            #pragma unroll
            for (int k = 1; k < 8; ++k) {
                u64 cv = *(const u64*)(slast + (k * DV + j) * 2);
                accA = f2fma(mdA[k], cv, accA);
                accB = f2fma(mdB[k], cv, accB);
            }
            YlA[j] = accA; YlB[j] = accB;
        }
        u64 oA = f2fma(fdup(xa.w), YlA[3],
                 f2fma(fdup(xa.z), YlA[2],
                 f2fma(fdup(xa.y), YlA[1],
                 f2mul(fdup(xa.x), YlA[0]))));
        u64 oB = f2fma(fdup(xb.w), YlB[3],
                 f2fma(fdup(xb.z), YlB[2],
                 f2fma(fdup(xb.y), YlB[1],
                 f2mul(fdup(xb.x), YlB[0]))));
        float r0, r1;
        funpack(oA, r0, r1);
        { float2 res; res.x = r0; res.y = r1; *(float2*)(out + 2 * (size_t)n0) = res; }
        funpack(oB, r0, r1);
        { float2 res; res.x = r0; res.y = r1; *(float2*)(out + 2 * (size_t)n1) = res; }
    }
}

extern "C" void kernel_launch(void* const* d_in, const int* in_sizes, int n_in,
                              void* d_out, int out_size)
{
    const float* x  = (const float*)d_in[0];
    const float* cf = (const float*)d_in[1];
    const float* cm = (const float*)d_in[2];
    const float* cl = (const float*)d_in[3];
    float* out = (float*)d_out;

    const int n_total = in_sizes[0] / (LV * DV);   // 65536

    cudaFuncSetAttribute(tt_chain_kernel,
                         cudaFuncAttributeMaxDynamicSharedMemorySize, SMEM_BYTES);

    const int threads = 128;
    const int blocks = (n_total + 255) / 256;      // 2 samples per thread
    tt_chain_kernel<<<blocks, threads, SMEM_BYTES>>>(x, cf, cm, cl, out, n_total);
}

// round 4
// speedup vs baseline: 1.0263x; 1.0263x over previous
#include <cuda_runtime.h>

// SGD_Hankel TT-chain: N=65536, L=128, D=4, R=8, O=2.  S=2 samples/thread.
// R4: revert to R2 x-staging (LDG+STS refill, known good); add explicit
// software pipelining of core LDS at half-j-block granularity (double-
// buffered 16xu64 register buffers, cross-step prefetch into a padded
// score slot) so LDS latency never blocks FFMA2 issue.

#define DV 4
#define RV 8
#define LV 128
#define NSTEP 126
#define HALF  63

typedef unsigned long long u64;

__device__ __forceinline__ u64 fpack(float a, float b) {
    u64 r; asm("mov.b64 %0, {%1,%2};" : "=l"(r) : "f"(a), "f"(b)); return r;
}
__device__ __forceinline__ u64 fdup(float a) {
    u64 r; asm("mov.b64 %0, {%1,%1};" : "=l"(r) : "f"(a)); return r;
}
__device__ __forceinline__ void funpack(u64 v, float& a, float& b) {
    asm("mov.b64 {%0,%1}, %2;" : "=f"(a), "=f"(b) : "l"(v));
}
__device__ __forceinline__ u64 f2mul(u64 a, u64 b) {
    u64 d; asm("mul.rn.f32x2 %0, %1, %2;" : "=l"(d) : "l"(a), "l"(b)); return d;
}
__device__ __forceinline__ u64 f2fma(u64 a, u64 b, u64 c) {
    u64 d; asm("fma.rn.f32x2 %0, %1, %2, %3;" : "=l"(d) : "l"(a), "l"(b), "l"(c)); return d;
}

// smem: cores [64(63+1 pad)][3][8][8] + xbuf 4 warps * 2048 + first/last
#define SCORE_FLOATS (64 * 3 * RV * RV)        // 12288 (incl. 1 pad step)
#define XBUF_FLOATS  (4 * 2048)                // 8192
#define SFL_OFF      (SCORE_FLOATS + XBUF_FLOATS)
#define SMEM_FLOATS  (SFL_OFF + 96)
#define SMEM_BYTES   (SMEM_FLOATS * 4)         // 82304

// R2's known-good warp-level x refill: 8 steps x 64 rows, coalesced LDG.128
// + conflict-free swizzled STS.32.  (N exact -> no guards.)
__device__ __forceinline__ void refill_chunk(const float* __restrict__ x, float* xw,
                                             int base_w, int lane, int c)
{
    const int s8 = lane & 7;
    const int g  = lane >> 3;
    const int sw = s8 << 2;
    #pragma unroll
    for (int it = 0; it < 16; ++it) {
        int r = g + it * 4;                           // local row 0..63
        int n = base_w + ((r & 32) ? (r - 32 + 128) : r);
        float4 v = *(const float4*)(x + (size_t)n * (LV * DV) + (c * 8 + s8) * 4);
        int ridx = (r ^ sw) + s8 * 64;
        xw[0 * 512 + ridx] = v.x;
        xw[1 * 512 + ridx] = v.y;
        xw[2 * 512 + ridx] = v.z;
        xw[3 * 512 + ridx] = v.w;
    }
}

// Load one half-j-block (4 k-rows of 8 l's) into 16 u64 register pairs.
__device__ __forceinline__ void load_hb(u64 (&buf)[16], const float* p) {
    #pragma unroll
    for (int kk = 0; kk < 4; ++kk) {
        ulonglong2 t0 = *(const ulonglong2*)(p + kk * 8);
        ulonglong2 t1 = *(const ulonglong2*)(p + kk * 8 + 4);
        buf[kk * 4 + 0] = t0.x; buf[kk * 4 + 1] = t0.y;
        buf[kk * 4 + 2] = t1.x; buf[kk * 4 + 3] = t1.y;
    }
}

// FMA one half-block into Y accumulators. INIT: first half (k=0 seeds via mul).
template<bool INIT>
__device__ __forceinline__ void fma_hb(const u64 (&buf)[16],
                                       const u64 (&mdA)[8], const u64 (&mdB)[8],
                                       u64 (&YA)[4], u64 (&YB)[4], int kbase)
{
    #pragma unroll
    for (int kk = 0; kk < 4; ++kk) {
        const int k = kbase + kk;
        #pragma unroll
        for (int p = 0; p < 4; ++p) {
            if (INIT && kk == 0) {
                YA[p] = f2mul(mdA[k], buf[kk * 4 + p]);
                YB[p] = f2mul(mdB[k], buf[kk * 4 + p]);
            } else {
                YA[p] = f2fma(mdA[k], buf[kk * 4 + p], YA[p]);
                YB[p] = f2fma(mdB[k], buf[kk * 4 + p], YB[p]);
            }
        }
    }
}

extern "C" __global__ void __launch_bounds__(128, 2)
tt_chain_kernel(const float* __restrict__ x,
                const float* __restrict__ core_first,
                const float* __restrict__ cores_mid,
                const float* __restrict__ core_last,
                float* __restrict__ out,
                int n_total)
{
    extern __shared__ float sm[];
    float* score  = sm;                    // [64][3][8][8] (step 63 = pad)
    float* xbuf   = sm + SCORE_FLOATS;
    float* sfirst = sm + SFL_OFF;          // 32 floats [j][k]
    float* slast  = sfirst + 32;           // 64 floats [k][j][l]

    const int tid  = threadIdx.x;
    const int lane = tid & 31;
    const int w    = tid >> 5;
    float* xw = xbuf + w * 2048;

    const int base_w = blockIdx.x * 256 + w * 32;
    const int n0 = blockIdx.x * 256 + tid;
    const int n1 = n0 + 128;

    if (tid < 32)       sfirst[tid] = core_first[tid];
    else if (tid < 96)  slast[tid - 32] = core_last[tid - 32];

    u64 mpA[4], mpB[4];
    u64 mdA[8], mdB[8];
    u64 bufA[16], bufB[16];

    #pragma unroll 1
    for (int phase = 0; phase < 2; ++phase) {
        __syncthreads();    // prior-phase consumers done before core overwrite
        // stage cores for this phase: [s][k][j][l] -> [s][j][k][l], j<3
        for (int u = tid; u < HALF * 48; u += 128) {
            int st = u / 48;
            int rr = u - st * 48;
            int j = rr >> 4, k = (rr >> 1) & 7, h = rr & 1;
            float4 v = *(const float4*)(cores_mid
                        + (((size_t)(phase * HALF + st) * RV + k) * DV + j) * RV + h * 4);
            *(float4*)(score + ((st * 3 + j) * RV + k) * RV + h * 4) = v;
        }
        __syncthreads();

        if (phase == 0) {
            refill_chunk(x, xw, base_w, lane, 0);
            __syncwarp();
            float xa0 = xw[lane],        xa1 = xw[512 + lane],
                  xa2 = xw[1024 + lane], xa3 = xw[1536 + lane];
            float xb0 = xw[32 + lane],        xb1 = xw[512 + 32 + lane],
                  xb2 = xw[1024 + 32 + lane], xb3 = xw[1536 + 32 + lane];
            float mA[8], mB[8];
            #pragma unroll
            for (int k = 0; k < 8; ++k) {
                mA[k] = sfirst[k] * xa0 + sfirst[8 + k] * xa1
                      + sfirst[16 + k] * xa2 + sfirst[24 + k] * xa3;
                mB[k] = sfirst[k] * xb0 + sfirst[8 + k] * xb1
                      + sfirst[16 + k] * xb2 + sfirst[24 + k] * xb3;
            }
            #pragma unroll
            for (int p = 0; p < 4; ++p) {
                mpA[p] = fpack(mA[2 * p], mA[2 * p + 1]);
                mpB[p] = fpack(mB[2 * p], mB[2 * p + 1]);
            }
            #pragma unroll
            for (int k = 0; k < 8; ++k) { mdA[k] = fdup(mA[k]); mdB[k] = fdup(mB[k]); }
        }

        // prime the pipeline: (step 0, j0, k-lo)
        load_hb(bufA, score);

        const float* cp = score;
        #pragma unroll 1
        for (int sc = 0; sc < HALF; ++sc) {
            const int l = phase * HALF + sc + 1;       // x index consumed this step
            if ((l & 7) == 0) {
                __syncwarp();
                refill_chunk(x, xw, base_w, lane, l >> 3);
                __syncwarp();
            }
            const int s8 = l & 7;
            const int ia = (lane ^ (s8 << 2)) + s8 * 64;
            float xa0 = xw[ia],        xa1 = xw[512 + ia],
                  xa2 = xw[1024 + ia], xa3 = xw[1536 + ia];
            float xb0 = xw[32 + ia],        xb1 = xw[512 + 32 + ia],
                  xb2 = xw[1024 + 32 + ia], xb3 = xw[1536 + 32 + ia];

            u64 YA[4], YB[4], accA[4], accB[4];

            // j0
            load_hb(bufB, cp + 32);                    // j0 k-hi
            fma_hb<true>(bufA, mdA, mdB, YA, YB, 0);
            load_hb(bufA, cp + 64);                    // j1 k-lo
            fma_hb<false>(bufB, mdA, mdB, YA, YB, 4);
            {
                const u64 a0 = fdup(xa0), b0 = fdup(xb0);
                #pragma unroll
                for (int p = 0; p < 4; ++p) {
                    accA[p] = f2mul(a0, YA[p]);
                    accB[p] = f2mul(b0, YB[p]);
                }
            }
            // j1
            load_hb(bufB, cp + 96);                    // j1 k-hi
            fma_hb<true>(bufA, mdA, mdB, YA, YB, 0);
            load_hb(bufA, cp + 128);                   // j2 k-lo
            fma_hb<false>(bufB, mdA, mdB, YA, YB, 4);
            {
                const u64 a1 = fdup(xa1), b1 = fdup(xb1);
                #pragma unroll
                for (int p = 0; p < 4; ++p) {
                    accA[p] = f2fma(a1, YA[p], accA[p]);
                    accB[p] = f2fma(b1, YB[p], accB[p]);
                }
            }
            // j2
            load_hb(bufB, cp + 160);                   // j2 k-hi
            fma_hb<true>(bufA, mdA, mdB, YA, YB, 0);
            load_hb(bufA, cp + 192);                   // NEXT step j0 k-lo (pad-safe)
            fma_hb<false>(bufB, mdA, mdB, YA, YB, 4);
            {
                const u64 a2 = fdup(xa2), b2 = fdup(xb2);
                const u64 a3 = fdup(xa3), b3 = fdup(xb3);
                #pragma unroll
                for (int p = 0; p < 4; ++p) {
                    accA[p] = f2fma(a2, YA[p], accA[p]);
                    accB[p] = f2fma(b2, YB[p], accB[p]);
                    // identity slice: j=3 term is x3 * merged (exact)
                    mpA[p] = f2fma(a3, mpA[p], accA[p]);
                    mpB[p] = f2fma(b3, mpB[p], accB[p]);
                }
            }
            // refresh duplicated merged for next step
            #pragma unroll
            for (int p = 0; p < 4; ++p) {
                float u0, u1, v0, v1;
                funpack(mpA[p], u0, u1);
                funpack(mpB[p], v0, v1);
                mdA[2 * p] = fdup(u0); mdA[2 * p + 1] = fdup(u1);
                mdB[2 * p] = fdup(v0); mdB[2 * p + 1] = fdup(v1);
            }
            cp += 192;
        }
    }

    // ---- final contraction: out[l] = sum_j x_j (sum_k m_k core_last[k][j][l]) ----
    {
        const int l = LV - 1;                  // 127, chunk 15 still staged
        const int s8 = l & 7;
        const int ia = (lane ^ (s8 << 2)) + s8 * 64;
        float xa0 = xw[ia],        xa1 = xw[512 + ia],
              xa2 = xw[1024 + ia], xa3 = xw[1536 + ia];
        float xb0 = xw[32 + ia],        xb1 = xw[512 + 32 + ia],
              xb2 = xw[1024 + 32 + ia], xb3 = xw[1536 + 32 + ia];

        u64 YlA[4], YlB[4];
        #pragma unroll
        for (int j = 0; j < 4; ++j) {
            u64 accA = f2mul(mdA[0], *(const u64*)(slast + j * 2));
            u64 accB = f2mul(mdB[0], *(const u64*)(slast + j * 2));
            #pragma unroll
            for (int k = 1; k < 8; ++k) {
                u64 cv = *(const u64*)(slast + (k * DV + j) * 2);
                accA = f2fma(mdA[k], cv, accA);
                accB = f2fma(mdB[k], cv, accB);
            }
            YlA[j] = accA; YlB[j] = accB;
        }
        u64 oA = f2fma(fdup(xa3), YlA[3],
                 f2fma(fdup(xa2), YlA[2],
                 f2fma(fdup(xa1), YlA[1],
                 f2mul(fdup(xa0), YlA[0]))));
        u64 oB = f2fma(fdup(xb3), YlB[3],
                 f2fma(fdup(xb2), YlB[2],
                 f2fma(fdup(xb1), YlB[1],
                 f2mul(fdup(xb0), YlB[0]))));
        float r0, r1;
        funpack(oA, r0, r1);
        { float2 res; res.x = r0; res.y = r1; *(float2*)(out + 2 * (size_t)n0) = res; }
        funpack(oB, r0, r1);
        { float2 res; res.x = r0; res.y = r1; *(float2*)(out + 2 * (size_t)n1) = res; }
    }
}

extern "C" void kernel_launch(void* const* d_in, const int* in_sizes, int n_in,
                              void* d_out, int out_size)
{
    const float* x  = (const float*)d_in[0];
    const float* cf = (const float*)d_in[1];
    const float* cm = (const float*)d_in[2];
    const float* cl = (const float*)d_in[3];
    float* out = (float*)d_out;

    const int n_total = in_sizes[0] / (LV * DV);   // 65536

    cudaFuncSetAttribute(tt_chain_kernel,
                         cudaFuncAttributeMaxDynamicSharedMemorySize, SMEM_BYTES);

    const int threads = 128;
    const int blocks = (n_total + 255) / 256;      // 2 samples per thread
    tt_chain_kernel<<<blocks, threads, SMEM_BYTES>>>(x, cf, cm, cl, out, n_total);
}